// round 11
// baseline (speedup 1.0000x reference)
#include <cuda_runtime.h>
#include <math.h>

#define B_   128
#define P_   2048
#define NB_  2000
#define NF_  250
#define NC_  16
#define R_   128
#define LS_  1750      // NB - NF
#define FT_  1751      // NB - NF + 1
#define NW_  63        // 32-bit words covering NB=2000
#define NWP_ 64        // padded row stride in words

// ---------------- scratch (static device globals; no allocations) ----------------
__device__ float d_filt[FT_];
__device__ float d_stimdot[B_];
__device__ float d_gensig[B_ * LS_];
__device__ unsigned d_bm[B_ * NC_ * NWP_];   // bitmask of cc != 0

// ---------------- K-prep: fused pack + filt + stimdot (dispatch by blockIdx) ----
// blocks [0, PACK_BLKS): k_pack       (256 thr: 8 warps, one word each)
// blocks [PACK_BLKS, +FILT_BLKS): k_filt (one warp per t)
// last STIM_BLKS blocks: k_stimdot    (one warp per b)
#define PACK_BLKS  ((B_ * NC_ * NW_ * 32 + 255) / 256)   // 16128
#define FILT_BLKS  ((FT_ * 32 + 255) / 256)              // 219
#define STIM_BLKS  ((B_ * 32 + 255) / 256)               // 16

__global__ void __launch_bounds__(256)
k_prep(const float* __restrict__ cc,
       const float* __restrict__ stim_time,
       const float* __restrict__ stf,
       const float* __restrict__ spat,
       const float* __restrict__ sf) {
    const int blk = blockIdx.x;
    const int lane = threadIdx.x & 31;

    if (blk < PACK_BLKS) {
        int gid  = blk * 256 + threadIdx.x;
        int warp = gid >> 5;
        int row  = warp / NW_;
        int word = warp - row * NW_;
        if (row >= B_ * NC_) return;
        int elem = word * 32 + lane;
        float v = (elem < NB_) ? cc[(size_t)row * NB_ + elem] : 0.0f;
        unsigned m = __ballot_sync(0xffffffffu, v != 0.0f);
        if (lane == 0) d_bm[row * NWP_ + word] = m;
    } else if (blk < PACK_BLKS + FILT_BLKS) {
        int warp = ((blk - PACK_BLKS) * 256 + threadIdx.x) >> 5;
        if (warp >= FT_) return;
        double a = 0.0;
        #pragma unroll
        for (int i = lane; i < NF_; i += 32)
            a += (double)stim_time[warp + i] * (double)stf[i];
        #pragma unroll
        for (int m = 16; m; m >>= 1) a += __shfl_xor_sync(0xffffffffu, a, m);
        if (lane == 0) d_filt[warp] = (float)a;
    } else {
        int warp = ((blk - PACK_BLKS - FILT_BLKS) * 256 + threadIdx.x) >> 5;
        if (warp >= B_) return;
        const float* row = spat + (size_t)warp * P_;
        double a = 0.0;
        for (int p = lane; p < P_; p += 32)
            a += (double)row[p] * (double)sf[p];
        #pragma unroll
        for (int m = 16; m; m >>= 1) a += __shfl_xor_sync(0xffffffffu, a, m);
        if (lane == 0) d_stimdot[warp] = (float)a;
    }
}

// ---------------- K3: gensig — 2 threads per t (8 cells each), 512-thr blocks ----
// Same 256-t/block smem footprint; halves the per-thread divergent-loop chain
// and doubles warps/SMSP for latency hiding. Pair combine via one double shfl
// (double reassociation only — bit-safe per R2..R10 evidence).
__global__ void __launch_bounds__(512)
k_gensig(const float* __restrict__ cK,
         const float* __restrict__ bias) {
    __shared__ double sKd[NC_ * 256];          // taps zero-padded 250 -> 256
    __shared__ unsigned sbm[NC_ * NWP_];

    const int tid = threadIdx.x;
    const int b   = blockIdx.y;

    for (int i = tid; i < NC_ * 256; i += 512) {
        int c = i >> 8, k = i & 255;
        sKd[i] = (k < NF_) ? (double)cK[c * NF_ + k] : 0.0;
    }
    for (int i = tid; i < NC_ * NWP_; i += 512)
        sbm[i] = d_bm[b * NC_ * NWP_ + i];
    __syncthreads();

    const int cg = tid & 1;                    // cell half: c in [8cg, 8cg+8)
    const int t  = blockIdx.x * 256 + (tid >> 1);

    double a0 = 0.0, a1 = 0.0, a2 = 0.0, a3 = 0.0;
    double a4 = 0.0, a5 = 0.0, a6 = 0.0, a7 = 0.0;
    if (t < LS_) {
        const int w0 = t >> 5;
        const int o  = t & 31;
        #pragma unroll 1
        for (int c = cg * 8; c < cg * 8 + 8; ++c) {
            const unsigned* bm = sbm + c * NWP_ + w0;
            const double*   kd = sKd + c * 256;
            unsigned m0 = __funnelshift_r(bm[0], bm[1], o);
            unsigned m1 = __funnelshift_r(bm[1], bm[2], o);
            unsigned m2 = __funnelshift_r(bm[2], bm[3], o);
            unsigned m3 = __funnelshift_r(bm[3], bm[4], o);
            unsigned m4 = __funnelshift_r(bm[4], bm[5], o);
            unsigned m5 = __funnelshift_r(bm[5], bm[6], o);
            unsigned m6 = __funnelshift_r(bm[6], bm[7], o);
            unsigned m7 = __funnelshift_r(bm[7], bm[8], o);
            while (m0) { int i = __ffs(m0) - 1; m0 &= m0 - 1; a0 += kd[  0 + i]; }
            while (m1) { int i = __ffs(m1) - 1; m1 &= m1 - 1; a1 += kd[ 32 + i]; }
            while (m2) { int i = __ffs(m2) - 1; m2 &= m2 - 1; a2 += kd[ 64 + i]; }
            while (m3) { int i = __ffs(m3) - 1; m3 &= m3 - 1; a3 += kd[ 96 + i]; }
            while (m4) { int i = __ffs(m4) - 1; m4 &= m4 - 1; a4 += kd[128 + i]; }
            while (m5) { int i = __ffs(m5) - 1; m5 &= m5 - 1; a5 += kd[160 + i]; }
            while (m6) { int i = __ffs(m6) - 1; m6 &= m6 - 1; a6 += kd[192 + i]; }
            while (m7) { int i = __ffs(m7) - 1; m7 &= m7 - 1; a7 += kd[224 + i]; }
        }
    }
    double tot = (((a0 + a1) + (a2 + a3)) + ((a4 + a5) + (a6 + a7)));
    tot += __shfl_xor_sync(0xffffffffu, tot, 1);

    if (cg == 0 && t < LS_) {
        float coup = (float)tot;
        float sg = __fmul_rn(d_stimdot[b], d_filt[t]);
        sg = __fadd_rn(sg, bias[0]);
        d_gensig[b * LS_ + t] = __fadd_rn(sg, coup);
    }
}

// ---------------- K4: simulation — R3 version verbatim (frozen; ~700us) --------
__global__ void __launch_bounds__(128)
k_sim(const float* __restrict__ init,
      const float* __restrict__ ff,
      const float* __restrict__ u,
      float* __restrict__ out) {
    const unsigned FULL = 0xffffffffu;
    const int lane = threadIdx.x & 31;
    const int gw   = (blockIdx.x * blockDim.x + threadIdx.x) >> 5;  // 0..4095
    const int b    = gw >> 5;         // 32 warps per b
    const int rq   = gw & 31;
    const int half = lane >> 3;       // 0..3: sequence within the warp
    const int q    = lane & 7;        // lane within the 8-lane group
    const int seq  = b * R_ + rq * 4 + half;

    float f[32], w[32];
    #pragma unroll
    for (int i = 0; i < 32; ++i) {
        int k = q * 32 + i;
        bool valid = (k < NF_);
        f[i] = valid ? ff[k] : 0.0f;
        w[i] = valid ? init[b * NF_ + k] : 0.0f;
    }

    float* orow = out + (size_t)seq * NB_;
    for (int k = q; k < NF_; k += 8)
        orow[k] = init[b * NF_ + k];

    const float* gens = d_gensig + b * LS_;
    const int src_half  = lane & 24;
    const int src_shift = src_half | ((q + 1) & 7);

    for (int t0 = 0; t0 < LS_; t0 += 32) {
        float gval = (t0 + lane < LS_) ? gens[t0 + lane] : 0.0f;
        float uval[4], outv[4];
        #pragma unroll
        for (int m = 0; m < 4; ++m) {
            int t = t0 + 8 * m + q;
            uval[m] = (t < LS_) ? u[(size_t)t * (B_ * R_) + seq] : 0.0f;
            outv[m] = 0.0f;
        }

        #pragma unroll
        for (int s = 0; s < 32; ++s) {
            float a  = w[s & 31]        * f[0];
            float bb = w[(16 + s) & 31] * f[16];
            #pragma unroll
            for (int i = 1; i < 16; ++i) {
                a  = fmaf(w[(i + s) & 31],      f[i],      a);
                bb = fmaf(w[(16 + i + s) & 31], f[16 + i], bb);
            }
            float acc = a + bb;
            acc += __shfl_xor_sync(FULL, acc, 1);
            acc += __shfl_xor_sync(FULL, acc, 2);
            acc += __shfl_xor_sync(FULL, acc, 4);

            float gt = __shfl_sync(FULL, gval, s);
            float ut = __shfl_sync(FULL, uval[s >> 3], src_half | (s & 7));

            float g = gt + acc;
            float e = expf(-g);
            float sig = 1.0f / (1.0f + e);
            float spike = (ut < sig) ? 1.0f : 0.0f;

            if (q == (s & 7)) outv[s >> 3] = spike;

            float inc = __shfl_sync(FULL, w[s & 31], src_shift);
            w[s & 31] = inc;
            if (q == 7) w[(s + 26) & 31] = spike;
        }

        #pragma unroll
        for (int m = 0; m < 4; ++m) {
            int t = t0 + 8 * m + q;
            if (t < LS_) orow[NF_ + t] = outv[m];
        }
    }
}

// ---------------- launch ----------------
extern "C" void kernel_launch(void* const* d_in, const int* in_sizes, int n_in,
                              void* d_out, int out_size) {
    (void)in_sizes; (void)n_in; (void)out_size;
    const float* stim_spat = (const float*)d_in[0];
    const float* stim_time = (const float*)d_in[1];
    const float* init      = (const float*)d_in[2];
    const float* cc        = (const float*)d_in[3];
    const float* sf        = (const float*)d_in[4];
    const float* bias      = (const float*)d_in[5];
    const float* stf       = (const float*)d_in[6];
    const float* ff        = (const float*)d_in[7];
    const float* cK        = (const float*)d_in[8];
    const float* u         = (const float*)d_in[9];
    float* out = (float*)d_out;

    // fused prep: pack + filt + stimdot
    k_prep<<<PACK_BLKS + FILT_BLKS + STIM_BLKS, 256>>>(cc, stim_time, stf,
                                                       stim_spat, sf);

    dim3 g3((LS_ + 255) / 256, B_);
    k_gensig<<<g3, 512>>>(cK, bias);

    // 4096 warps (4 sequences each) -> 1024 blocks of 128 threads
    k_sim<<<1024, 128>>>(init, ff, u, out);
}

// round 12
// speedup vs baseline: 1.0264x; 1.0264x over previous
#include <cuda_runtime.h>
#include <math.h>

#define B_   128
#define P_   2048
#define NB_  2000
#define NF_  250
#define NC_  16
#define R_   128
#define LS_  1750      // NB - NF
#define FT_  1751      // NB - NF + 1
#define NW_  63        // 32-bit words covering NB=2000
#define NWP_ 64        // padded row stride in words

// ---------------- scratch (static device globals; no allocations) ----------------
__device__ float d_filt[FT_];
__device__ float d_stimdot[B_];
__device__ float d_gensig[B_ * LS_];
__device__ unsigned d_bm[B_ * NC_ * NWP_];   // bitmask of cc != 0

// ---------------- K-prep: fused pack + filt + stimdot (dispatch by blockIdx) ----
#define PACK_BLKS  ((B_ * NC_ * NW_ * 32 + 255) / 256)   // 16128
#define FILT_BLKS  ((FT_ * 32 + 255) / 256)              // 219
#define STIM_BLKS  ((B_ * 32 + 255) / 256)               // 16

__global__ void __launch_bounds__(256)
k_prep(const float* __restrict__ cc,
       const float* __restrict__ stim_time,
       const float* __restrict__ stf,
       const float* __restrict__ spat,
       const float* __restrict__ sf) {
    const int blk = blockIdx.x;
    const int lane = threadIdx.x & 31;

    if (blk < PACK_BLKS) {
        int gid  = blk * 256 + threadIdx.x;
        int warp = gid >> 5;
        int row  = warp / NW_;
        int word = warp - row * NW_;
        if (row >= B_ * NC_) return;
        int elem = word * 32 + lane;
        float v = (elem < NB_) ? cc[(size_t)row * NB_ + elem] : 0.0f;
        unsigned m = __ballot_sync(0xffffffffu, v != 0.0f);
        if (lane == 0) d_bm[row * NWP_ + word] = m;
    } else if (blk < PACK_BLKS + FILT_BLKS) {
        int warp = ((blk - PACK_BLKS) * 256 + threadIdx.x) >> 5;
        if (warp >= FT_) return;
        double a = 0.0;
        #pragma unroll
        for (int i = lane; i < NF_; i += 32)
            a += (double)stim_time[warp + i] * (double)stf[i];
        #pragma unroll
        for (int m = 16; m; m >>= 1) a += __shfl_xor_sync(0xffffffffu, a, m);
        if (lane == 0) d_filt[warp] = (float)a;
    } else {
        int warp = ((blk - PACK_BLKS - FILT_BLKS) * 256 + threadIdx.x) >> 5;
        if (warp >= B_) return;
        const float* row = spat + (size_t)warp * P_;
        double a = 0.0;
        for (int p = lane; p < P_; p += 32)
            a += (double)row[p] * (double)sf[p];
        #pragma unroll
        for (int m = 16; m; m >>= 1) a += __shfl_xor_sync(0xffffffffu, a, m);
        if (lane == 0) d_stimdot[warp] = (float)a;
    }
}

// ---------------- K3: gensig — R10 verified version (256 thr, 8 accumulators) ----
__global__ void __launch_bounds__(256)
k_gensig(const float* __restrict__ cK,
         const float* __restrict__ bias) {
    __shared__ double sKd[NC_ * 256];          // taps zero-padded 250 -> 256
    __shared__ unsigned sbm[NC_ * NWP_];

    const int tid = threadIdx.x;
    const int b   = blockIdx.y;

    for (int i = tid; i < NC_ * 256; i += 256) {
        int c = i >> 8, k = i & 255;
        sKd[i] = (k < NF_) ? (double)cK[c * NF_ + k] : 0.0;
    }
    for (int i = tid; i < NC_ * NWP_; i += 256)
        sbm[i] = d_bm[b * NC_ * NWP_ + i];
    __syncthreads();

    const int t = blockIdx.x * 256 + tid;
    if (t >= LS_) return;

    const int w0 = t >> 5;
    const int o  = t & 31;

    double a0 = 0.0, a1 = 0.0, a2 = 0.0, a3 = 0.0;
    double a4 = 0.0, a5 = 0.0, a6 = 0.0, a7 = 0.0;
    #pragma unroll 1
    for (int c = 0; c < NC_; ++c) {
        const unsigned* bm = sbm + c * NWP_ + w0;
        const double*   kd = sKd + c * 256;
        unsigned m0 = __funnelshift_r(bm[0], bm[1], o);
        unsigned m1 = __funnelshift_r(bm[1], bm[2], o);
        unsigned m2 = __funnelshift_r(bm[2], bm[3], o);
        unsigned m3 = __funnelshift_r(bm[3], bm[4], o);
        unsigned m4 = __funnelshift_r(bm[4], bm[5], o);
        unsigned m5 = __funnelshift_r(bm[5], bm[6], o);
        unsigned m6 = __funnelshift_r(bm[6], bm[7], o);
        unsigned m7 = __funnelshift_r(bm[7], bm[8], o);
        while (m0) { int i = __ffs(m0) - 1; m0 &= m0 - 1; a0 += kd[  0 + i]; }
        while (m1) { int i = __ffs(m1) - 1; m1 &= m1 - 1; a1 += kd[ 32 + i]; }
        while (m2) { int i = __ffs(m2) - 1; m2 &= m2 - 1; a2 += kd[ 64 + i]; }
        while (m3) { int i = __ffs(m3) - 1; m3 &= m3 - 1; a3 += kd[ 96 + i]; }
        while (m4) { int i = __ffs(m4) - 1; m4 &= m4 - 1; a4 += kd[128 + i]; }
        while (m5) { int i = __ffs(m5) - 1; m5 &= m5 - 1; a5 += kd[160 + i]; }
        while (m6) { int i = __ffs(m6) - 1; m6 &= m6 - 1; a6 += kd[192 + i]; }
        while (m7) { int i = __ffs(m7) - 1; m7 &= m7 - 1; a7 += kd[224 + i]; }
    }
    float coup = (float)(((a0 + a1) + (a2 + a3)) + ((a4 + a5) + (a6 + a7)));
    float sg = __fmul_rn(d_stimdot[b], d_filt[t]);
    sg = __fadd_rn(sg, bias[0]);
    d_gensig[b * LS_ + t] = __fadd_rn(sg, coup);
}

// ---------------- K4: simulation — R3 arithmetic verbatim, 64-thread blocks ----
// No smem, no block syncs: 64-thr blocks pack 11 blocks/SM (22 warps) vs 5x128
// (20 warps) at ~90 regs — finer allocation granularity, zero other change.
__global__ void __launch_bounds__(64)
k_sim(const float* __restrict__ init,
      const float* __restrict__ ff,
      const float* __restrict__ u,
      float* __restrict__ out) {
    const unsigned FULL = 0xffffffffu;
    const int lane = threadIdx.x & 31;
    const int gw   = (blockIdx.x * blockDim.x + threadIdx.x) >> 5;  // 0..4095
    const int b    = gw >> 5;         // 32 warps per b
    const int rq   = gw & 31;
    const int half = lane >> 3;       // 0..3: sequence within the warp
    const int q    = lane & 7;        // lane within the 8-lane group
    const int seq  = b * R_ + rq * 4 + half;

    float f[32], w[32];
    #pragma unroll
    for (int i = 0; i < 32; ++i) {
        int k = q * 32 + i;
        bool valid = (k < NF_);
        f[i] = valid ? ff[k] : 0.0f;
        w[i] = valid ? init[b * NF_ + k] : 0.0f;
    }

    float* orow = out + (size_t)seq * NB_;
    for (int k = q; k < NF_; k += 8)
        orow[k] = init[b * NF_ + k];

    const float* gens = d_gensig + b * LS_;
    const int src_half  = lane & 24;
    const int src_shift = src_half | ((q + 1) & 7);

    for (int t0 = 0; t0 < LS_; t0 += 32) {
        float gval = (t0 + lane < LS_) ? gens[t0 + lane] : 0.0f;
        float uval[4], outv[4];
        #pragma unroll
        for (int m = 0; m < 4; ++m) {
            int t = t0 + 8 * m + q;
            uval[m] = (t < LS_) ? u[(size_t)t * (B_ * R_) + seq] : 0.0f;
            outv[m] = 0.0f;
        }

        #pragma unroll
        for (int s = 0; s < 32; ++s) {
            float a  = w[s & 31]        * f[0];
            float bb = w[(16 + s) & 31] * f[16];
            #pragma unroll
            for (int i = 1; i < 16; ++i) {
                a  = fmaf(w[(i + s) & 31],      f[i],      a);
                bb = fmaf(w[(16 + i + s) & 31], f[16 + i], bb);
            }
            float acc = a + bb;
            acc += __shfl_xor_sync(FULL, acc, 1);
            acc += __shfl_xor_sync(FULL, acc, 2);
            acc += __shfl_xor_sync(FULL, acc, 4);

            float gt = __shfl_sync(FULL, gval, s);
            float ut = __shfl_sync(FULL, uval[s >> 3], src_half | (s & 7));

            float g = gt + acc;
            float e = expf(-g);
            float sig = 1.0f / (1.0f + e);
            float spike = (ut < sig) ? 1.0f : 0.0f;

            if (q == (s & 7)) outv[s >> 3] = spike;

            float inc = __shfl_sync(FULL, w[s & 31], src_shift);
            w[s & 31] = inc;
            if (q == 7) w[(s + 26) & 31] = spike;
        }

        #pragma unroll
        for (int m = 0; m < 4; ++m) {
            int t = t0 + 8 * m + q;
            if (t < LS_) orow[NF_ + t] = outv[m];
        }
    }
}

// ---------------- launch ----------------
extern "C" void kernel_launch(void* const* d_in, const int* in_sizes, int n_in,
                              void* d_out, int out_size) {
    (void)in_sizes; (void)n_in; (void)out_size;
    const float* stim_spat = (const float*)d_in[0];
    const float* stim_time = (const float*)d_in[1];
    const float* init      = (const float*)d_in[2];
    const float* cc        = (const float*)d_in[3];
    const float* sf        = (const float*)d_in[4];
    const float* bias      = (const float*)d_in[5];
    const float* stf       = (const float*)d_in[6];
    const float* ff        = (const float*)d_in[7];
    const float* cK        = (const float*)d_in[8];
    const float* u         = (const float*)d_in[9];
    float* out = (float*)d_out;

    // fused prep: pack + filt + stimdot
    k_prep<<<PACK_BLKS + FILT_BLKS + STIM_BLKS, 256>>>(cc, stim_time, stf,
                                                       stim_spat, sf);

    dim3 g3((LS_ + 255) / 256, B_);
    k_gensig<<<g3, 256>>>(cK, bias);

    // 4096 warps (4 sequences each) -> 2048 blocks of 64 threads
    k_sim<<<2048, 64>>>(init, ff, u, out);
}